// round 5
// baseline (speedup 1.0000x reference)
#include <cuda_runtime.h>
#include <cuda_bf16.h>
#include <math.h>
#include <stdint.h>

// ---------------- dims ----------------
#define BATCH 8
#define SEQ   1024
#define DMODEL 1024
#define NHEADS 16
#define DQKV  64
#define DFF   4096
#define NLAYERS 6
#define BL    (BATCH*SEQ)          // 8192
#define D3    (3*DMODEL)           // 3072

typedef __nv_bfloat16 bf16;

// ---------------- scratch ----------------
__device__ float g_h  [BL*DMODEL];
__device__ float g_tmp[BL*DMODEL];
__device__ float g_qkv[BL*D3];
__device__ float g_pe [SEQ*DMODEL];
__device__ unsigned long long g_mb[BL*(SEQ/64)];

// split activations
__device__ bf16 g_hh [BL*DMODEL];
__device__ bf16 g_hl [BL*DMODEL];
__device__ bf16 g_cxh[BL*DMODEL];
__device__ bf16 g_cxl[BL*DMODEL];
__device__ bf16 g_ffh[BL*DFF];
__device__ bf16 g_ffl[BL*DFF];

// transposed + split weights (bf16 hi/lo), layout [N][K] K-major
//   q/k/v: layer i -> i*3M + {0,1,2}M   (18M)   (contiguous => fused QKV N=3072)
//   Wo:    18M + i*1M                    (6M)
//   FF1:   24M + i*4M  ([4096][1024])    (24M)
//   FF2:   48M + i*4M  ([1024][4096])    (24M)
#define WT_TOTAL (72u*1048576u)
__device__ bf16 g_wt_hi[WT_TOTAL];
__device__ bf16 g_wt_lo[WT_TOTAL];

// ================= PTX helpers =================
__device__ __forceinline__ uint32_t smem_u32(const void* p) {
    uint32_t a;
    asm("{ .reg .u64 t; cvta.to.shared.u64 t, %1; cvt.u32.u64 %0, t; }" : "=r"(a) : "l"(p));
    return a;
}
__device__ __forceinline__ void cp16(uint32_t s, const void* g) {
    asm volatile("cp.async.cg.shared.global [%0], [%1], 16;" :: "r"(s), "l"(g));
}
__device__ __forceinline__ void cp_commit() { asm volatile("cp.async.commit_group;"); }
template <int N> __device__ __forceinline__ void cp_wait() {
    asm volatile("cp.async.wait_group %0;" :: "n"(N));
}
__device__ __forceinline__ void ldm4(uint32_t& r0, uint32_t& r1, uint32_t& r2, uint32_t& r3, uint32_t a) {
    asm volatile("ldmatrix.sync.aligned.m8n8.x4.shared.b16 {%0,%1,%2,%3}, [%4];"
        : "=r"(r0), "=r"(r1), "=r"(r2), "=r"(r3) : "r"(a));
}
__device__ __forceinline__ void mma16816(float* c, uint32_t a0, uint32_t a1, uint32_t a2, uint32_t a3,
                                         uint32_t b0, uint32_t b1) {
    asm volatile("mma.sync.aligned.m16n8k16.row.col.f32.bf16.bf16.f32 "
        "{%0,%1,%2,%3}, {%4,%5,%6,%7}, {%8,%9}, {%0,%1,%2,%3};"
        : "+f"(c[0]), "+f"(c[1]), "+f"(c[2]), "+f"(c[3])
        : "r"(a0), "r"(a1), "r"(a2), "r"(a3), "r"(b0), "r"(b1));
}
__device__ __forceinline__ uint32_t pack_split2(float v0, float v1, uint32_t& lo_out) {
    bf16 h0 = __float2bfloat16(v0);
    bf16 h1 = __float2bfloat16(v1);
    bf16 l0 = __float2bfloat16(v0 - __bfloat162float(h0));
    bf16 l1 = __float2bfloat16(v1 - __bfloat162float(h1));
    uint32_t hi = ((uint32_t)*(uint16_t*)&h1 << 16) | *(uint16_t*)&h0;
    lo_out = ((uint32_t)*(uint16_t*)&l1 << 16) | *(uint16_t*)&l0;
    return hi;
}

// ---------------- positional encoding ----------------
__global__ void pe_kernel(float* pe) {
    int idx = blockIdx.x * blockDim.x + threadIdx.x;
    int l = idx >> 10;
    int c = idx & 1023;
    double p = (double)(c & ~1) / (double)DMODEL;
    double divisor = pow(10000.0, p);
    double ang = (double)(l + 1) / divisor;
    pe[idx] = (float)((c & 1) ? cos(ang) : sin(ang));
}

// ---------------- mask -> bit words ----------------
__global__ void maskbits_kernel(const int* __restrict__ mask, unsigned long long* __restrict__ mb) {
    int warp = (blockIdx.x * blockDim.x + threadIdx.x) >> 5;
    int lane = threadIdx.x & 31;
    const int nwarps = gridDim.x * blockDim.x / 32;
    for (int w = warp; w < BL * (SEQ/64); w += nwarps) {
        int row = w >> 4;
        int kt  = w & 15;
        size_t base = (size_t)row * SEQ + kt * 64;
        int m0 = mask[base + lane];
        int m1 = mask[base + 32 + lane];
        unsigned lo = __ballot_sync(0xffffffffu, m0 != 0);
        unsigned hi = __ballot_sync(0xffffffffu, m1 != 0);
        if (lane == 0) mb[w] = (unsigned long long)lo | ((unsigned long long)hi << 32);
    }
}

// ---------------- embedding + PE (+ split) ----------------
__global__ void embed_kernel(const int* __restrict__ x, const float* __restrict__ embed,
                             const float* __restrict__ pe, float* __restrict__ h,
                             bf16* __restrict__ Hh, bf16* __restrict__ Hl) {
    int r = blockIdx.x;
    int t = threadIdx.x;
    int l = r & 1023;
    int tok = x[r];
    float4 e  = *(const float4*)(embed + (size_t)tok * DMODEL + t * 4);
    float4 pp = *(const float4*)(pe + (size_t)l * DMODEL + t * 4);
    float4 o;
    o.x = e.x * 32.0f + pp.x;
    o.y = e.y * 32.0f + pp.y;
    o.z = e.z * 32.0f + pp.z;
    o.w = e.w * 32.0f + pp.w;
    *(float4*)(h + (size_t)r * DMODEL + t * 4) = o;
    uint32_t hi0, hi1, lo0, lo1;
    hi0 = pack_split2(o.x, o.y, lo0);
    hi1 = pack_split2(o.z, o.w, lo1);
    uint2 hv = {hi0, hi1}, lv = {lo0, lo1};
    *(uint2*)(Hh + (size_t)r * DMODEL + t * 4) = hv;
    *(uint2*)(Hl + (size_t)r * DMODEL + t * 4) = lv;
}

// ---------------- weight transpose + bf16 split ----------------
__global__ void tsplit_kernel(const float* __restrict__ W, bf16* __restrict__ Oh, bf16* __restrict__ Ol,
                              int K, int N, int mode) {
    __shared__ float tile[32][33];
    int n0 = blockIdx.x * 32, k0 = blockIdx.y * 32;
    int tx = threadIdx.x, ty = threadIdx.y;    // 32 x 8
#pragma unroll
    for (int i = 0; i < 32; i += 8) {
        int k = k0 + ty + i, n = n0 + tx;
        float v;
        if (mode == 0) v = W[(size_t)k * N + n];
        else v = W[(size_t)(n >> 6) * (K * 64) + (size_t)k * 64 + (n & 63)];
        tile[ty + i][tx] = v;
    }
    __syncthreads();
#pragma unroll
    for (int i = 0; i < 32; i += 8) {
        int n = n0 + ty + i, k = k0 + tx;
        float v = tile[tx][ty + i];
        bf16 hi = __float2bfloat16(v);
        bf16 lo = __float2bfloat16(v - __bfloat162float(hi));
        Oh[(size_t)n * K + k] = hi;
        Ol[(size_t)n * K + k] = lo;
    }
}

// ---------------- HMMA GEMM, 4-stage cp.async pipeline ----------------
// C[M,N] = A * B^T with A = Ah+Al [M][K], B = Bh+Bl [N][K], 3-term split.
// Output: C fp32 (bias/res/relu) and/or split bf16 (Oh/Ol, after bias/relu).
#define BMT 128
#define BNT 128
#define BKC 32
#define TSTRIDE 40                         // bf16 per smem row (pad 8)
#define TILEB (BMT * TSTRIDE * 2)          // 10240 B
#define STAGEB (4 * TILEB)                 // 40960 B
#define NSTAGE 4
#define GSMEM (NSTAGE * STAGEB)            // 163840 B

__global__ void __launch_bounds__(256)
gemm_mma(const bf16* __restrict__ Ah, const bf16* __restrict__ Al,
         const bf16* __restrict__ Bh, const bf16* __restrict__ Bl,
         float* __restrict__ C, bf16* __restrict__ Oh, bf16* __restrict__ Ol,
         int N, int K,
         const float* __restrict__ bias, const float* __restrict__ res, int relu) {
    extern __shared__ char smem[];
    const uint32_t sbase = smem_u32(smem);
    const int t = threadIdx.x;
    const int wid = t >> 5, lane = t & 31;
    const int wm = wid >> 2, wn = wid & 3;       // 2 x 4 warps
    const int row0 = blockIdx.y * BMT, col0 = blockIdx.x * BNT;

    const bf16* srcs[4];
    srcs[0] = Ah + (size_t)row0 * K;
    srcs[1] = Al + (size_t)row0 * K;
    srcs[2] = Bh + (size_t)col0 * K;
    srcs[3] = Bl + (size_t)col0 * K;

    const int nst = K / BKC;
    const int lrow0 = t >> 2, lchunk = t & 3;

    auto load_stage = [&](int kc, int buf) {
        uint32_t sb = sbase + buf * STAGEB;
#pragma unroll
        for (int m = 0; m < 4; ++m) {
            const bf16* g = srcs[m] + (size_t)kc * BKC;
            uint32_t tb = sb + m * TILEB;
#pragma unroll
            for (int hlf = 0; hlf < 2; ++hlf) {
                int row = lrow0 + hlf * 64;
                cp16(tb + (row * TSTRIDE + lchunk * 8) * 2,
                     g + (size_t)row * K + lchunk * 8);
            }
        }
        cp_commit();
    };

    float acc[4][4][4];
#pragma unroll
    for (int i = 0; i < 4; ++i)
#pragma unroll
        for (int j = 0; j < 4; ++j)
#pragma unroll
            for (int r = 0; r < 4; ++r) acc[i][j][r] = 0.f;

    const int lrow = lane & 15;
    const int lcol = (lane >> 4) << 3;

    load_stage(0, 0);
    load_stage(1, 1);
    load_stage(2, 2);

    for (int kc = 0; kc < nst; ++kc) {
        int buf = kc & 3;
        cp_wait<2>();
        __syncthreads();
        if (kc + 3 < nst) load_stage(kc + 3, (kc + 3) & 3);

        uint32_t sb = sbase + buf * STAGEB;
        uint32_t sAh = sb;
        uint32_t sAl = sb + TILEB;
        uint32_t sBh = sb + 2 * TILEB;
        uint32_t sBl = sb + 3 * TILEB;

#pragma unroll
        for (int ks = 0; ks < 2; ++ks) {
            int kof = ks * 16 + lcol;
            uint32_t ah[4][4], al[4][4];
#pragma unroll
            for (int mi = 0; mi < 4; ++mi) {
                int row = wm * 64 + mi * 16 + lrow;
                uint32_t off = (row * TSTRIDE + kof) * 2;
                ldm4(ah[mi][0], ah[mi][1], ah[mi][2], ah[mi][3], sAh + off);
                ldm4(al[mi][0], al[mi][1], al[mi][2], al[mi][3], sAl + off);
            }
            uint32_t bh[2][4], bl[2][4];
#pragma unroll
            for (int nh = 0; nh < 2; ++nh) {
                int row = wn * 32 + nh * 16 + lrow;
                uint32_t off = (row * TSTRIDE + kof) * 2;
                ldm4(bh[nh][0], bh[nh][1], bh[nh][2], bh[nh][3], sBh + off);
                ldm4(bl[nh][0], bl[nh][1], bl[nh][2], bl[nh][3], sBl + off);
            }
#pragma unroll
            for (int mi = 0; mi < 4; ++mi) {
#pragma unroll
                for (int ni = 0; ni < 4; ++ni) {
                    int nh = ni >> 1, np = ni & 1;
                    uint32_t b0h = bh[nh][np], b1h = bh[nh][np + 2];
                    uint32_t b0l = bl[nh][np], b1l = bl[nh][np + 2];
                    mma16816(acc[mi][ni], ah[mi][0], ah[mi][1], ah[mi][2], ah[mi][3], b0h, b1h);
                    mma16816(acc[mi][ni], ah[mi][0], ah[mi][1], ah[mi][2], ah[mi][3], b0l, b1l);
                    mma16816(acc[mi][ni], al[mi][0], al[mi][1], al[mi][2], al[mi][3], b0h, b1h);
                }
            }
        }
        __syncthreads();
    }

    // epilogue
    const int erow = lane >> 2, ecol = (lane & 3) * 2;
#pragma unroll
    for (int mi = 0; mi < 4; ++mi) {
#pragma unroll
        for (int p = 0; p < 2; ++p) {
            int r = row0 + wm * 64 + mi * 16 + p * 8 + erow;
            const float* rrow = res ? res + (size_t)r * N : (const float*)0;
#pragma unroll
            for (int ni = 0; ni < 4; ++ni) {
                int c = col0 + wn * 32 + ni * 8 + ecol;
                float v0 = acc[mi][ni][p * 2 + 0];
                float v1 = acc[mi][ni][p * 2 + 1];
                if (bias) { v0 += bias[c]; v1 += bias[c + 1]; }
                if (rrow) {
                    float2 rv = *(const float2*)(rrow + c);
                    v0 += rv.x; v1 += rv.y;
                }
                if (relu) { v0 = fmaxf(v0, 0.f); v1 = fmaxf(v1, 0.f); }
                if (C) {
                    float2 o = {v0, v1};
                    *(float2*)(C + (size_t)r * N + c) = o;
                }
                if (Oh) {
                    uint32_t lo, hi = pack_split2(v0, v1, lo);
                    *(uint32_t*)(Oh + (size_t)r * N + c) = hi;
                    *(uint32_t*)(Ol + (size_t)r * N + c) = lo;
                }
            }
        }
    }
}

// ---------------- flash attention (fp32, split ctx output) ----------------
#define QSW(d, r) (((d) << 6) + (((((r) >> 2) ^ ((d) & 15))) << 2) + ((r) & 3))

__global__ void __launch_bounds__(256)
flash_kernel(const float* __restrict__ qkv, const unsigned long long* __restrict__ mb,
             bf16* __restrict__ cxh, bf16* __restrict__ cxl) {
    extern __shared__ float sm[];
    float* Qs = sm;
    float* Ks = Qs + 4096;
    float* Vs = Ks + 4096;
    float* Ss = Vs + 4096;
    float* rowM = Ss + 64 * 65;
    float* rowL = rowM + 64;
    float* rowA = rowL + 64;

    int b = blockIdx.z, hh = blockIdx.y, qt = blockIdx.x;
    int t = threadIdx.x, tx = t & 15, ty = t >> 4;
    int rowbase = b * SEQ + qt * 64;
    const float* qbase = qkv + (size_t)rowbase * D3 + hh * 64;

#pragma unroll
    for (int it = 0; it < 4; ++it) {
        int f = t + it * 256;
        int r = f >> 4;
        int d4 = (f & 15) << 2;
        float4 val = *(const float4*)(qbase + (size_t)r * D3 + d4);
        Qs[QSW(d4 + 0, r)] = val.x;
        Qs[QSW(d4 + 1, r)] = val.y;
        Qs[QSW(d4 + 2, r)] = val.z;
        Qs[QSW(d4 + 3, r)] = val.w;
    }
    if (t < 64) { rowM[t] = -INFINITY; rowL[t] = 0.f; }

    float o[4][4];
#pragma unroll
    for (int i = 0; i < 4; ++i)
#pragma unroll
        for (int j = 0; j < 4; ++j) o[i][j] = 0.f;

    const unsigned long long* mrow = mb + (size_t)rowbase * (SEQ / 64);

    for (int kt = 0; kt < SEQ / 64; ++kt) {
        __syncthreads();
        const float* kbase = qkv + (size_t)(b * SEQ + kt * 64) * D3 + DMODEL + hh * 64;
        const float* vbase = qkv + (size_t)(b * SEQ + kt * 64) * D3 + 2 * DMODEL + hh * 64;
#pragma unroll
        for (int it = 0; it < 4; ++it) {
            int f = t + it * 256;
            int r = f >> 4;
            int d4 = (f & 15) << 2;
            float4 kv4 = *(const float4*)(kbase + (size_t)r * D3 + d4);
            Ks[QSW(d4 + 0, r)] = kv4.x;
            Ks[QSW(d4 + 1, r)] = kv4.y;
            Ks[QSW(d4 + 2, r)] = kv4.z;
            Ks[QSW(d4 + 3, r)] = kv4.w;
            float4 vv = *(const float4*)(vbase + (size_t)r * D3 + d4);
            *(float4*)(Vs + r * 64 + d4) = vv;
        }
        __syncthreads();

        float s[4][4];
#pragma unroll
        for (int i = 0; i < 4; ++i)
#pragma unroll
            for (int j = 0; j < 4; ++j) s[i][j] = 0.f;
#pragma unroll 8
        for (int d = 0; d < 64; ++d) {
            float4 a4 = *(const float4*)(Qs + (d << 6) + ((ty ^ (d & 15)) << 2));
            float4 b4 = *(const float4*)(Ks + (d << 6) + ((tx ^ (d & 15)) << 2));
            float a[4] = {a4.x, a4.y, a4.z, a4.w};
            float bb[4] = {b4.x, b4.y, b4.z, b4.w};
#pragma unroll
            for (int i = 0; i < 4; ++i)
#pragma unroll
                for (int j = 0; j < 4; ++j) s[i][j] = fmaf(a[i], bb[j], s[i][j]);
        }
#pragma unroll
        for (int i = 0; i < 4; ++i) {
            int ri = ty * 4 + i;
            unsigned long long wbits = mrow[ri * (SEQ / 64) + kt];
#pragma unroll
            for (int j = 0; j < 4; ++j) {
                int cj = tx * 4 + j;
                float vv = s[i][j] * 0.125f;
                if (!((wbits >> cj) & 1ULL)) vv = -1e9f;
                Ss[ri * 65 + cj] = vv;
            }
        }
        __syncthreads();

        // online softmax: 4 threads per row
        {
            int r = t >> 2, sub = t & 3;
            float* srow = Ss + r * 65 + sub * 16;
            float mold = rowM[r];
            float mx = mold;
#pragma unroll
            for (int j = 0; j < 16; ++j) mx = fmaxf(mx, srow[j]);
            mx = fmaxf(mx, __shfl_xor_sync(0xffffffffu, mx, 1));
            mx = fmaxf(mx, __shfl_xor_sync(0xffffffffu, mx, 2));
            float sum = 0.f;
#pragma unroll
            for (int j = 0; j < 16; ++j) {
                float p = expf(srow[j] - mx);
                srow[j] = p;
                sum += p;
            }
            sum += __shfl_xor_sync(0xffffffffu, sum, 1);
            sum += __shfl_xor_sync(0xffffffffu, sum, 2);
            if (sub == 0) {
                float alpha = expf(mold - mx);
                rowL[r] = rowL[r] * alpha + sum;
                rowM[r] = mx;
                rowA[r] = alpha;
            }
        }
        __syncthreads();

        float al[4];
#pragma unroll
        for (int i = 0; i < 4; ++i) al[i] = rowA[ty * 4 + i];
#pragma unroll
        for (int i = 0; i < 4; ++i)
#pragma unroll
            for (int j = 0; j < 4; ++j) o[i][j] *= al[i];
#pragma unroll 8
        for (int j = 0; j < 64; ++j) {
            float p0 = Ss[(ty * 4 + 0) * 65 + j];
            float p1 = Ss[(ty * 4 + 1) * 65 + j];
            float p2 = Ss[(ty * 4 + 2) * 65 + j];
            float p3 = Ss[(ty * 4 + 3) * 65 + j];
            float4 vv = *(const float4*)(Vs + j * 64 + tx * 4);
            o[0][0] = fmaf(p0, vv.x, o[0][0]); o[0][1] = fmaf(p0, vv.y, o[0][1]);
            o[0][2] = fmaf(p0, vv.z, o[0][2]); o[0][3] = fmaf(p0, vv.w, o[0][3]);
            o[1][0] = fmaf(p1, vv.x, o[1][0]); o[1][1] = fmaf(p1, vv.y, o[1][1]);
            o[1][2] = fmaf(p1, vv.z, o[1][2]); o[1][3] = fmaf(p1, vv.w, o[1][3]);
            o[2][0] = fmaf(p2, vv.x, o[2][0]); o[2][1] = fmaf(p2, vv.y, o[2][1]);
            o[2][2] = fmaf(p2, vv.z, o[2][2]); o[2][3] = fmaf(p2, vv.w, o[2][3]);
            o[3][0] = fmaf(p3, vv.x, o[3][0]); o[3][1] = fmaf(p3, vv.y, o[3][1]);
            o[3][2] = fmaf(p3, vv.z, o[3][2]); o[3][3] = fmaf(p3, vv.w, o[3][3]);
        }
    }
    __syncthreads();
#pragma unroll
    for (int i = 0; i < 4; ++i) {
        float inv = 1.f / rowL[ty * 4 + i];
        int grow = rowbase + ty * 4 + i;
        float v0 = o[i][0] * inv, v1 = o[i][1] * inv, v2 = o[i][2] * inv, v3 = o[i][3] * inv;
        uint32_t lo0, lo1;
        uint32_t hi0 = pack_split2(v0, v1, lo0);
        uint32_t hi1 = pack_split2(v2, v3, lo1);
        uint2 hv = {hi0, hi1}, lv = {lo0, lo1};
        size_t off = (size_t)grow * DMODEL + hh * 64 + tx * 4;
        *(uint2*)(cxh + off) = hv;
        *(uint2*)(cxl + off) = lv;
    }
}

// ---------------- layernorm (+ optional split out) ----------------
__global__ void layernorm_kernel(const float* __restrict__ X, const float* __restrict__ s,
                                 const float* __restrict__ bvec, float* __restrict__ Y,
                                 bf16* __restrict__ Yh, bf16* __restrict__ Yl) {
    __shared__ float red[256];
    int r = blockIdx.x;
    int t = threadIdx.x;
    float4 v = *(const float4*)(X + (size_t)r * DMODEL + t * 4);
    float ssum = v.x + v.y + v.z + v.w;
    red[t] = ssum;
    __syncthreads();
    for (int off = 128; off > 0; off >>= 1) {
        if (t < off) red[t] += red[t + off];
        __syncthreads();
    }
    float mu = red[0] * (1.f / DMODEL);
    __syncthreads();
    float d0 = v.x - mu, d1 = v.y - mu, d2 = v.z - mu, d3 = v.w - mu;
    red[t] = d0 * d0 + d1 * d1 + d2 * d2 + d3 * d3;
    __syncthreads();
    for (int off = 128; off > 0; off >>= 1) {
        if (t < off) red[t] += red[t + off];
        __syncthreads();
    }
    float var = red[0] * (1.f / DMODEL);
    float rs = rsqrtf(var + 1e-5f);
    float4 sc = *(const float4*)(s + t * 4);
    float4 be = *(const float4*)(bvec + t * 4);
    float4 out;
    out.x = d0 * rs * sc.x + be.x;
    out.y = d1 * rs * sc.y + be.y;
    out.z = d2 * rs * sc.z + be.z;
    out.w = d3 * rs * sc.w + be.w;
    *(float4*)(Y + (size_t)r * DMODEL + t * 4) = out;
    uint32_t lo0, lo1;
    uint32_t hi0 = pack_split2(out.x, out.y, lo0);
    uint32_t hi1 = pack_split2(out.z, out.w, lo1);
    uint2 hv = {hi0, hi1}, lv = {lo0, lo1};
    *(uint2*)(Yh + (size_t)r * DMODEL + t * 4) = hv;
    *(uint2*)(Yl + (size_t)r * DMODEL + t * 4) = lv;
}

// ---------------- output head ----------------
__global__ void head_kernel(const float* __restrict__ h, const float* __restrict__ ow,
                            const float* __restrict__ ob, float* __restrict__ out) {
    int t = threadIdx.x;
    int b = t >> 4, a = t & 15;
    const float* hrow = h + (size_t)(b * SEQ + (SEQ - 1)) * DMODEL;
    float acc = 0.f;
    for (int m = 0; m < DMODEL; ++m) acc = fmaf(hrow[m], ow[m * 16 + a], acc);
    acc += ob[a];
    float mx = acc;
    for (int off = 8; off > 0; off >>= 1)
        mx = fmaxf(mx, __shfl_xor_sync(0xffffffffu, mx, off));
    float e = expf(acc - mx);
    float sum = e;
    for (int off = 8; off > 0; off >>= 1)
        sum += __shfl_xor_sync(0xffffffffu, sum, off);
    out[b * 16 + a] = acc - mx - logf(sum);
}

// ---------------- launch ----------------
#define M1 1048576u

extern "C" void kernel_launch(void* const* d_in, const int* in_sizes, int n_in,
                              void* d_out, int out_size) {
    const int*   x     = (const int*)d_in[0];
    const int*   mask  = (const int*)d_in[1];
    const float* embed = (const float*)d_in[2];
    const float* Wq    = (const float*)d_in[3];
    const float* Wk    = (const float*)d_in[4];
    const float* Wv    = (const float*)d_in[5];
    const float* Wo_w  = (const float*)d_in[6];
    const float* Wo_b  = (const float*)d_in[7];
    const float* ln1_s = (const float*)d_in[8];
    const float* ln1_b = (const float*)d_in[9];
    const float* ff_w1 = (const float*)d_in[10];
    const float* ff_b1 = (const float*)d_in[11];
    const float* ff_w2 = (const float*)d_in[12];
    const float* ff_b2 = (const float*)d_in[13];
    const float* ln2_s = (const float*)d_in[14];
    const float* ln2_b = (const float*)d_in[15];
    const float* out_w = (const float*)d_in[16];
    const float* out_b = (const float*)d_in[17];
    float* out = (float*)d_out;

    float *h, *tmp, *qkv, *pe;
    unsigned long long* mb;
    bf16 *wtH, *wtL, *hH, *hL, *cxH, *cxL, *ffH, *ffL;
    cudaGetSymbolAddress((void**)&h,   g_h);
    cudaGetSymbolAddress((void**)&tmp, g_tmp);
    cudaGetSymbolAddress((void**)&qkv, g_qkv);
    cudaGetSymbolAddress((void**)&pe,  g_pe);
    cudaGetSymbolAddress((void**)&mb,  g_mb);
    cudaGetSymbolAddress((void**)&wtH, g_wt_hi);
    cudaGetSymbolAddress((void**)&wtL, g_wt_lo);
    cudaGetSymbolAddress((void**)&hH,  g_hh);
    cudaGetSymbolAddress((void**)&hL,  g_hl);
    cudaGetSymbolAddress((void**)&cxH, g_cxh);
    cudaGetSymbolAddress((void**)&cxL, g_cxl);
    cudaGetSymbolAddress((void**)&ffH, g_ffh);
    cudaGetSymbolAddress((void**)&ffL, g_ffl);

    const int flash_smem = (4096 * 3 + 64 * 65 + 3 * 64) * 4;
    cudaFuncSetAttribute(flash_kernel, cudaFuncAttributeMaxDynamicSharedMemorySize, flash_smem);
    cudaFuncSetAttribute(gemm_mma, cudaFuncAttributeMaxDynamicSharedMemorySize, GSMEM);

    pe_kernel<<<(SEQ * DMODEL) / 256, 256>>>(pe);
    maskbits_kernel<<<512, 256>>>(mask, mb);
    embed_kernel<<<BL, 256>>>(x, embed, pe, h, hH, hL);

    // --- weight transpose + split ---
    dim3 tb(32, 8);
    for (int i = 0; i < NLAYERS; ++i) {
        size_t oq = (size_t)i * 3 * M1;
        tsplit_kernel<<<dim3(32, 32), tb>>>(Wq + (size_t)i * NHEADS * DMODEL * DQKV, wtH + oq,        wtL + oq,        DMODEL, DMODEL, 1);
        tsplit_kernel<<<dim3(32, 32), tb>>>(Wk + (size_t)i * NHEADS * DMODEL * DQKV, wtH + oq + M1,   wtL + oq + M1,   DMODEL, DMODEL, 1);
        tsplit_kernel<<<dim3(32, 32), tb>>>(Wv + (size_t)i * NHEADS * DMODEL * DQKV, wtH + oq + 2*M1, wtL + oq + 2*M1, DMODEL, DMODEL, 1);
        size_t oo = 18 * (size_t)M1 + (size_t)i * M1;
        tsplit_kernel<<<dim3(32, 32), tb>>>(Wo_w + (size_t)i * DMODEL * DMODEL, wtH + oo, wtL + oo, DMODEL, DMODEL, 0);
        size_t o1 = 24 * (size_t)M1 + (size_t)i * 4 * M1;
        tsplit_kernel<<<dim3(128, 32), tb>>>(ff_w1 + (size_t)i * DMODEL * DFF, wtH + o1, wtL + o1, DMODEL, DFF, 0);
        size_t o2 = 48 * (size_t)M1 + (size_t)i * 4 * M1;
        tsplit_kernel<<<dim3(32, 128), tb>>>(ff_w2 + (size_t)i * DFF * DMODEL, wtH + o2, wtL + o2, DFF, DMODEL, 0);
    }

    dim3 gQKV(D3 / BNT, BL / BMT);   // (24, 64)
    dim3 gD(DMODEL / BNT, BL / BMT); // (8, 64)
    dim3 gF(DFF / BNT, BL / BMT);    // (32, 64)

    for (int i = 0; i < NLAYERS; ++i) {
        size_t oq = (size_t)i * 3 * M1;
        size_t oo = 18 * (size_t)M1 + (size_t)i * M1;
        size_t o1 = 24 * (size_t)M1 + (size_t)i * 4 * M1;
        size_t o2 = 48 * (size_t)M1 + (size_t)i * 4 * M1;

        // fused QKV: [BL, 3072]
        gemm_mma<<<gQKV, 256, GSMEM>>>(hH, hL, wtH + oq, wtL + oq, qkv, nullptr, nullptr,
                                       D3, DMODEL, nullptr, nullptr, 0);

        flash_kernel<<<dim3(SEQ / 64, NHEADS, BATCH), 256, flash_smem>>>(qkv, mb, cxH, cxL);

        // Wo + residual -> tmp, then LN1 -> h + split
        gemm_mma<<<gD, 256, GSMEM>>>(cxH, cxL, wtH + oo, wtL + oo, tmp, nullptr, nullptr,
                                     DMODEL, DMODEL, Wo_b + (size_t)i * DMODEL, h, 0);
        layernorm_kernel<<<BL, 256>>>(tmp, ln1_s + (size_t)i * DMODEL, ln1_b + (size_t)i * DMODEL, h, hH, hL);

        // FF1 (relu) -> split only
        gemm_mma<<<gF, 256, GSMEM>>>(hH, hL, wtH + o1, wtL + o1, nullptr, ffH, ffL,
                                     DFF, DMODEL, ff_b1 + (size_t)i * DFF, nullptr, 1);
        // FF2 + residual -> tmp, then LN2 -> h + split
        gemm_mma<<<gD, 256, GSMEM>>>(ffH, ffL, wtH + o2, wtL + o2, tmp, nullptr, nullptr,
                                     DMODEL, DFF, ff_b2 + (size_t)i * DMODEL, h, 0);
        layernorm_kernel<<<BL, 256>>>(tmp, ln2_s + (size_t)i * DMODEL, ln2_b + (size_t)i * DMODEL, h, hH, hL);
    }

    head_kernel<<<1, 128>>>(h, out_w, out_b, out);
}

// round 6
// speedup vs baseline: 1.0829x; 1.0829x over previous
#include <cuda_runtime.h>
#include <cuda_bf16.h>
#include <math.h>
#include <stdint.h>

// ---------------- dims ----------------
#define BATCH 8
#define SEQ   1024
#define DMODEL 1024
#define NHEADS 16
#define DQKV  64
#define DFF   4096
#define NLAYERS 6
#define BL    (BATCH*SEQ)          // 8192
#define D3    (3*DMODEL)           // 3072

typedef __nv_bfloat16 bf16;

// ---------------- scratch ----------------
__device__ float g_h  [BL*DMODEL];
__device__ float g_tmp[BL*DMODEL];
__device__ float g_qkv[BL*D3];
__device__ float g_pe [SEQ*DMODEL];
__device__ unsigned long long g_mb[BL*(SEQ/64)];

// split activations
__device__ bf16 g_hh [BL*DMODEL];
__device__ bf16 g_hl [BL*DMODEL];
__device__ bf16 g_cxh[BL*DMODEL];
__device__ bf16 g_cxl[BL*DMODEL];
__device__ bf16 g_ffh[BL*DFF];
__device__ bf16 g_ffl[BL*DFF];

// transposed + split weights (bf16 hi/lo), layout [N][K] K-major
//   q/k/v: layer i -> i*3M + {0,1,2}M   (18M)   (contiguous => fused QKV N=3072)
//   Wo:    18M + i*1M                    (6M)
//   FF1:   24M + i*4M  ([4096][1024])    (24M)
//   FF2:   48M + i*4M  ([1024][4096])    (24M)
#define WT_TOTAL (72u*1048576u)
__device__ bf16 g_wt_hi[WT_TOTAL];
__device__ bf16 g_wt_lo[WT_TOTAL];

// ================= PTX helpers =================
__device__ __forceinline__ uint32_t smem_u32(const void* p) {
    uint32_t a;
    asm("{ .reg .u64 t; cvta.to.shared.u64 t, %1; cvt.u32.u64 %0, t; }" : "=r"(a) : "l"(p));
    return a;
}
__device__ __forceinline__ void cp16(uint32_t s, const void* g) {
    asm volatile("cp.async.cg.shared.global [%0], [%1], 16;" :: "r"(s), "l"(g));
}
__device__ __forceinline__ void cp_commit() { asm volatile("cp.async.commit_group;"); }
template <int N> __device__ __forceinline__ void cp_wait() {
    asm volatile("cp.async.wait_group %0;" :: "n"(N));
}
__device__ __forceinline__ void ldm4(uint32_t& r0, uint32_t& r1, uint32_t& r2, uint32_t& r3, uint32_t a) {
    asm volatile("ldmatrix.sync.aligned.m8n8.x4.shared.b16 {%0,%1,%2,%3}, [%4];"
        : "=r"(r0), "=r"(r1), "=r"(r2), "=r"(r3) : "r"(a));
}
__device__ __forceinline__ void mma16816(float* c, uint32_t a0, uint32_t a1, uint32_t a2, uint32_t a3,
                                         uint32_t b0, uint32_t b1) {
    asm volatile("mma.sync.aligned.m16n8k16.row.col.f32.bf16.bf16.f32 "
        "{%0,%1,%2,%3}, {%4,%5,%6,%7}, {%8,%9}, {%0,%1,%2,%3};"
        : "+f"(c[0]), "+f"(c[1]), "+f"(c[2]), "+f"(c[3])
        : "r"(a0), "r"(a1), "r"(a2), "r"(a3), "r"(b0), "r"(b1));
}
__device__ __forceinline__ uint32_t pack_split2(float v0, float v1, uint32_t& lo_out) {
    bf16 h0 = __float2bfloat16(v0);
    bf16 h1 = __float2bfloat16(v1);
    bf16 l0 = __float2bfloat16(v0 - __bfloat162float(h0));
    bf16 l1 = __float2bfloat16(v1 - __bfloat162float(h1));
    uint32_t hi = ((uint32_t)*(uint16_t*)&h1 << 16) | *(uint16_t*)&h0;
    lo_out = ((uint32_t)*(uint16_t*)&l1 << 16) | *(uint16_t*)&l0;
    return hi;
}

// ---------------- positional encoding ----------------
__global__ void pe_kernel(float* pe) {
    int idx = blockIdx.x * blockDim.x + threadIdx.x;
    int l = idx >> 10;
    int c = idx & 1023;
    double p = (double)(c & ~1) / (double)DMODEL;
    double divisor = pow(10000.0, p);
    double ang = (double)(l + 1) / divisor;
    pe[idx] = (float)((c & 1) ? cos(ang) : sin(ang));
}

// ---------------- mask -> bit words ----------------
__global__ void maskbits_kernel(const int* __restrict__ mask, unsigned long long* __restrict__ mb) {
    int warp = (blockIdx.x * blockDim.x + threadIdx.x) >> 5;
    int lane = threadIdx.x & 31;
    const int nwarps = gridDim.x * blockDim.x / 32;
    for (int w = warp; w < BL * (SEQ/64); w += nwarps) {
        int row = w >> 4;
        int kt  = w & 15;
        size_t base = (size_t)row * SEQ + kt * 64;
        int m0 = mask[base + lane];
        int m1 = mask[base + 32 + lane];
        unsigned lo = __ballot_sync(0xffffffffu, m0 != 0);
        unsigned hi = __ballot_sync(0xffffffffu, m1 != 0);
        if (lane == 0) mb[w] = (unsigned long long)lo | ((unsigned long long)hi << 32);
    }
}

// ---------------- embedding + PE (+ split) ----------------
__global__ void embed_kernel(const int* __restrict__ x, const float* __restrict__ embed,
                             const float* __restrict__ pe, float* __restrict__ h,
                             bf16* __restrict__ Hh, bf16* __restrict__ Hl) {
    int r = blockIdx.x;
    int t = threadIdx.x;
    int l = r & 1023;
    int tok = x[r];
    float4 e  = *(const float4*)(embed + (size_t)tok * DMODEL + t * 4);
    float4 pp = *(const float4*)(pe + (size_t)l * DMODEL + t * 4);
    float4 o;
    o.x = e.x * 32.0f + pp.x;
    o.y = e.y * 32.0f + pp.y;
    o.z = e.z * 32.0f + pp.z;
    o.w = e.w * 32.0f + pp.w;
    *(float4*)(h + (size_t)r * DMODEL + t * 4) = o;
    uint32_t hi0, hi1, lo0, lo1;
    hi0 = pack_split2(o.x, o.y, lo0);
    hi1 = pack_split2(o.z, o.w, lo1);
    uint2 hv = {hi0, hi1}, lv = {lo0, lo1};
    *(uint2*)(Hh + (size_t)r * DMODEL + t * 4) = hv;
    *(uint2*)(Hl + (size_t)r * DMODEL + t * 4) = lv;
}

// ---------------- weight transpose + bf16 split ----------------
__global__ void tsplit_kernel(const float* __restrict__ W, bf16* __restrict__ Oh, bf16* __restrict__ Ol,
                              int K, int N, int mode) {
    __shared__ float tile[32][33];
    int n0 = blockIdx.x * 32, k0 = blockIdx.y * 32;
    int tx = threadIdx.x, ty = threadIdx.y;    // 32 x 8
#pragma unroll
    for (int i = 0; i < 32; i += 8) {
        int k = k0 + ty + i, n = n0 + tx;
        float v;
        if (mode == 0) v = W[(size_t)k * N + n];
        else v = W[(size_t)(n >> 6) * (K * 64) + (size_t)k * 64 + (n & 63)];
        tile[ty + i][tx] = v;
    }
    __syncthreads();
#pragma unroll
    for (int i = 0; i < 32; i += 8) {
        int n = n0 + ty + i, k = k0 + tx;
        float v = tile[tx][ty + i];
        bf16 hi = __float2bfloat16(v);
        bf16 lo = __float2bfloat16(v - __bfloat162float(hi));
        Oh[(size_t)n * K + k] = hi;
        Ol[(size_t)n * K + k] = lo;
    }
}

// ---------------- HMMA GEMM, 2-stage cp.async pipeline (R4 core) ----------------
// C[M,N] = A * B^T with A = Ah+Al [M][K], B = Bh+Bl [N][K], 3-term split.
// Output: C fp32 (bias/res/relu) and/or split bf16 (Oh/Ol, after bias/relu).
#define BMT 128
#define BNT 128
#define BKC 32
#define TSTRIDE 40                         // bf16 per smem row (pad 8)
#define TILEB (BMT * TSTRIDE * 2)          // 10240 B
#define STAGEB (4 * TILEB)                 // 40960 B
#define GSMEM (2 * STAGEB)                 // 81920 B

__global__ void __launch_bounds__(256)
gemm_mma(const bf16* __restrict__ Ah, const bf16* __restrict__ Al,
         const bf16* __restrict__ Bh, const bf16* __restrict__ Bl,
         float* __restrict__ C, bf16* __restrict__ Oh, bf16* __restrict__ Ol,
         int N, int K,
         const float* __restrict__ bias, const float* __restrict__ res, int relu) {
    extern __shared__ char smem[];
    const uint32_t sbase = smem_u32(smem);
    const int t = threadIdx.x;
    const int wid = t >> 5, lane = t & 31;
    const int wm = wid >> 2, wn = wid & 3;       // 2 x 4 warps
    const int row0 = blockIdx.y * BMT, col0 = blockIdx.x * BNT;

    const bf16* srcs[4];
    srcs[0] = Ah + (size_t)row0 * K;
    srcs[1] = Al + (size_t)row0 * K;
    srcs[2] = Bh + (size_t)col0 * K;
    srcs[3] = Bl + (size_t)col0 * K;

    const int nst = K / BKC;
    const int lrow0 = t >> 2, lchunk = t & 3;

    auto load_stage = [&](int kc, int buf) {
        uint32_t sb = sbase + buf * STAGEB;
#pragma unroll
        for (int m = 0; m < 4; ++m) {
            const bf16* g = srcs[m] + (size_t)kc * BKC;
            uint32_t tb = sb + m * TILEB;
#pragma unroll
            for (int hlf = 0; hlf < 2; ++hlf) {
                int row = lrow0 + hlf * 64;
                cp16(tb + (row * TSTRIDE + lchunk * 8) * 2,
                     g + (size_t)row * K + lchunk * 8);
            }
        }
        cp_commit();
    };

    float acc[4][4][4];
#pragma unroll
    for (int i = 0; i < 4; ++i)
#pragma unroll
        for (int j = 0; j < 4; ++j)
#pragma unroll
            for (int r = 0; r < 4; ++r) acc[i][j][r] = 0.f;

    const int lrow = lane & 15;
    const int lcol = (lane >> 4) << 3;

    load_stage(0, 0);

    for (int kc = 0; kc < nst; ++kc) {
        int buf = kc & 1;
        if (kc + 1 < nst) {
            load_stage(kc + 1, buf ^ 1);
            cp_wait<1>();
        } else {
            cp_wait<0>();
        }
        __syncthreads();

        uint32_t sb = sbase + buf * STAGEB;
        uint32_t sAh = sb;
        uint32_t sAl = sb + TILEB;
        uint32_t sBh = sb + 2 * TILEB;
        uint32_t sBl = sb + 3 * TILEB;

#pragma unroll
        for (int ks = 0; ks < 2; ++ks) {
            int kof = ks * 16 + lcol;
            uint32_t ah[4][4], al[4][4];
#pragma unroll
            for (int mi = 0; mi < 4; ++mi) {
                int row = wm * 64 + mi * 16 + lrow;
                uint32_t off = (row * TSTRIDE + kof) * 2;
                ldm4(ah[mi][0], ah[mi][1], ah[mi][2], ah[mi][3], sAh + off);
                ldm4(al[mi][0], al[mi][1], al[mi][2], al[mi][3], sAl + off);
            }
            uint32_t bh[2][4], bl[2][4];
#pragma unroll
            for (int nh = 0; nh < 2; ++nh) {
                int row = wn * 32 + nh * 16 + lrow;
                uint32_t off = (row * TSTRIDE + kof) * 2;
                ldm4(bh[nh][0], bh[nh][1], bh[nh][2], bh[nh][3], sBh + off);
                ldm4(bl[nh][0], bl[nh][1], bl[nh][2], bl[nh][3], sBl + off);
            }
#pragma unroll
            for (int mi = 0; mi < 4; ++mi) {
#pragma unroll
                for (int ni = 0; ni < 4; ++ni) {
                    int nh = ni >> 1, np = ni & 1;
                    uint32_t b0h = bh[nh][np], b1h = bh[nh][np + 2];
                    uint32_t b0l = bl[nh][np], b1l = bl[nh][np + 2];
                    mma16816(acc[mi][ni], ah[mi][0], ah[mi][1], ah[mi][2], ah[mi][3], b0h, b1h);
                    mma16816(acc[mi][ni], ah[mi][0], ah[mi][1], ah[mi][2], ah[mi][3], b0l, b1l);
                    mma16816(acc[mi][ni], al[mi][0], al[mi][1], al[mi][2], al[mi][3], b0h, b1h);
                }
            }
        }
        __syncthreads();
    }

    // epilogue
    const int erow = lane >> 2, ecol = (lane & 3) * 2;
#pragma unroll
    for (int mi = 0; mi < 4; ++mi) {
#pragma unroll
        for (int p = 0; p < 2; ++p) {
            int r = row0 + wm * 64 + mi * 16 + p * 8 + erow;
            const float* rrow = res ? res + (size_t)r * N : (const float*)0;
#pragma unroll
            for (int ni = 0; ni < 4; ++ni) {
                int c = col0 + wn * 32 + ni * 8 + ecol;
                float v0 = acc[mi][ni][p * 2 + 0];
                float v1 = acc[mi][ni][p * 2 + 1];
                if (bias) { v0 += bias[c]; v1 += bias[c + 1]; }
                if (rrow) {
                    float2 rv = *(const float2*)(rrow + c);
                    v0 += rv.x; v1 += rv.y;
                }
                if (relu) { v0 = fmaxf(v0, 0.f); v1 = fmaxf(v1, 0.f); }
                if (C) {
                    float2 o = {v0, v1};
                    *(float2*)(C + (size_t)r * N + c) = o;
                }
                if (Oh) {
                    uint32_t lo, hi = pack_split2(v0, v1, lo);
                    *(uint32_t*)(Oh + (size_t)r * N + c) = hi;
                    *(uint32_t*)(Ol + (size_t)r * N + c) = lo;
                }
            }
        }
    }
}

// ---------------- flash attention (fp32, split ctx output) ----------------
#define QSW(d, r) (((d) << 6) + (((((r) >> 2) ^ ((d) & 15))) << 2) + ((r) & 3))

__global__ void __launch_bounds__(256)
flash_kernel(const float* __restrict__ qkv, const unsigned long long* __restrict__ mb,
             bf16* __restrict__ cxh, bf16* __restrict__ cxl) {
    extern __shared__ float sm[];
    float* Qs = sm;
    float* Ks = Qs + 4096;
    float* Vs = Ks + 4096;
    float* Ss = Vs + 4096;
    float* rowM = Ss + 64 * 65;
    float* rowL = rowM + 64;
    float* rowA = rowL + 64;

    int b = blockIdx.z, hh = blockIdx.y, qt = blockIdx.x;
    int t = threadIdx.x, tx = t & 15, ty = t >> 4;
    int rowbase = b * SEQ + qt * 64;
    const float* qbase = qkv + (size_t)rowbase * D3 + hh * 64;

#pragma unroll
    for (int it = 0; it < 4; ++it) {
        int f = t + it * 256;
        int r = f >> 4;
        int d4 = (f & 15) << 2;
        float4 val = *(const float4*)(qbase + (size_t)r * D3 + d4);
        Qs[QSW(d4 + 0, r)] = val.x;
        Qs[QSW(d4 + 1, r)] = val.y;
        Qs[QSW(d4 + 2, r)] = val.z;
        Qs[QSW(d4 + 3, r)] = val.w;
    }
    if (t < 64) { rowM[t] = -INFINITY; rowL[t] = 0.f; }

    float o[4][4];
#pragma unroll
    for (int i = 0; i < 4; ++i)
#pragma unroll
        for (int j = 0; j < 4; ++j) o[i][j] = 0.f;

    const unsigned long long* mrow = mb + (size_t)rowbase * (SEQ / 64);

    for (int kt = 0; kt < SEQ / 64; ++kt) {
        __syncthreads();
        const float* kbase = qkv + (size_t)(b * SEQ + kt * 64) * D3 + DMODEL + hh * 64;
        const float* vbase = qkv + (size_t)(b * SEQ + kt * 64) * D3 + 2 * DMODEL + hh * 64;
#pragma unroll
        for (int it = 0; it < 4; ++it) {
            int f = t + it * 256;
            int r = f >> 4;
            int d4 = (f & 15) << 2;
            float4 kv4 = *(const float4*)(kbase + (size_t)r * D3 + d4);
            Ks[QSW(d4 + 0, r)] = kv4.x;
            Ks[QSW(d4 + 1, r)] = kv4.y;
            Ks[QSW(d4 + 2, r)] = kv4.z;
            Ks[QSW(d4 + 3, r)] = kv4.w;
            float4 vv = *(const float4*)(vbase + (size_t)r * D3 + d4);
            *(float4*)(Vs + r * 64 + d4) = vv;
        }
        __syncthreads();

        float s[4][4];
#pragma unroll
        for (int i = 0; i < 4; ++i)
#pragma unroll
            for (int j = 0; j < 4; ++j) s[i][j] = 0.f;
#pragma unroll 8
        for (int d = 0; d < 64; ++d) {
            float4 a4 = *(const float4*)(Qs + (d << 6) + ((ty ^ (d & 15)) << 2));
            float4 b4 = *(const float4*)(Ks + (d << 6) + ((tx ^ (d & 15)) << 2));
            float a[4] = {a4.x, a4.y, a4.z, a4.w};
            float bb[4] = {b4.x, b4.y, b4.z, b4.w};
#pragma unroll
            for (int i = 0; i < 4; ++i)
#pragma unroll
                for (int j = 0; j < 4; ++j) s[i][j] = fmaf(a[i], bb[j], s[i][j]);
        }
#pragma unroll
        for (int i = 0; i < 4; ++i) {
            int ri = ty * 4 + i;
            unsigned long long wbits = mrow[ri * (SEQ / 64) + kt];
#pragma unroll
            for (int j = 0; j < 4; ++j) {
                int cj = tx * 4 + j;
                float vv = s[i][j] * 0.125f;
                if (!((wbits >> cj) & 1ULL)) vv = -1e9f;
                Ss[ri * 65 + cj] = vv;
            }
        }
        __syncthreads();

        // online softmax: 4 threads per row
        {
            int r = t >> 2, sub = t & 3;
            float* srow = Ss + r * 65 + sub * 16;
            float mold = rowM[r];
            float mx = mold;
#pragma unroll
            for (int j = 0; j < 16; ++j) mx = fmaxf(mx, srow[j]);
            mx = fmaxf(mx, __shfl_xor_sync(0xffffffffu, mx, 1));
            mx = fmaxf(mx, __shfl_xor_sync(0xffffffffu, mx, 2));
            float sum = 0.f;
#pragma unroll
            for (int j = 0; j < 16; ++j) {
                float p = expf(srow[j] - mx);
                srow[j] = p;
                sum += p;
            }
            sum += __shfl_xor_sync(0xffffffffu, sum, 1);
            sum += __shfl_xor_sync(0xffffffffu, sum, 2);
            if (sub == 0) {
                float alpha = expf(mold - mx);
                rowL[r] = rowL[r] * alpha + sum;
                rowM[r] = mx;
                rowA[r] = alpha;
            }
        }
        __syncthreads();

        float al[4];
#pragma unroll
        for (int i = 0; i < 4; ++i) al[i] = rowA[ty * 4 + i];
#pragma unroll
        for (int i = 0; i < 4; ++i)
#pragma unroll
            for (int j = 0; j < 4; ++j) o[i][j] *= al[i];
#pragma unroll 8
        for (int j = 0; j < 64; ++j) {
            float p0 = Ss[(ty * 4 + 0) * 65 + j];
            float p1 = Ss[(ty * 4 + 1) * 65 + j];
            float p2 = Ss[(ty * 4 + 2) * 65 + j];
            float p3 = Ss[(ty * 4 + 3) * 65 + j];
            float4 vv = *(const float4*)(Vs + j * 64 + tx * 4);
            o[0][0] = fmaf(p0, vv.x, o[0][0]); o[0][1] = fmaf(p0, vv.y, o[0][1]);
            o[0][2] = fmaf(p0, vv.z, o[0][2]); o[0][3] = fmaf(p0, vv.w, o[0][3]);
            o[1][0] = fmaf(p1, vv.x, o[1][0]); o[1][1] = fmaf(p1, vv.y, o[1][1]);
            o[1][2] = fmaf(p1, vv.z, o[1][2]); o[1][3] = fmaf(p1, vv.w, o[1][3]);
            o[2][0] = fmaf(p2, vv.x, o[2][0]); o[2][1] = fmaf(p2, vv.y, o[2][1]);
            o[2][2] = fmaf(p2, vv.z, o[2][2]); o[2][3] = fmaf(p2, vv.w, o[2][3]);
            o[3][0] = fmaf(p3, vv.x, o[3][0]); o[3][1] = fmaf(p3, vv.y, o[3][1]);
            o[3][2] = fmaf(p3, vv.z, o[3][2]); o[3][3] = fmaf(p3, vv.w, o[3][3]);
        }
    }
    __syncthreads();
#pragma unroll
    for (int i = 0; i < 4; ++i) {
        float inv = 1.f / rowL[ty * 4 + i];
        int grow = rowbase + ty * 4 + i;
        float v0 = o[i][0] * inv, v1 = o[i][1] * inv, v2 = o[i][2] * inv, v3 = o[i][3] * inv;
        uint32_t lo0, lo1;
        uint32_t hi0 = pack_split2(v0, v1, lo0);
        uint32_t hi1 = pack_split2(v2, v3, lo1);
        uint2 hv = {hi0, hi1}, lv = {lo0, lo1};
        size_t off = (size_t)grow * DMODEL + hh * 64 + tx * 4;
        *(uint2*)(cxh + off) = hv;
        *(uint2*)(cxl + off) = lv;
    }
}

// ---------------- layernorm (+ split out) ----------------
__global__ void layernorm_kernel(const float* __restrict__ X, const float* __restrict__ s,
                                 const float* __restrict__ bvec, float* __restrict__ Y,
                                 bf16* __restrict__ Yh, bf16* __restrict__ Yl) {
    __shared__ float red[256];
    int r = blockIdx.x;
    int t = threadIdx.x;
    float4 v = *(const float4*)(X + (size_t)r * DMODEL + t * 4);
    float ssum = v.x + v.y + v.z + v.w;
    red[t] = ssum;
    __syncthreads();
    for (int off = 128; off > 0; off >>= 1) {
        if (t < off) red[t] += red[t + off];
        __syncthreads();
    }
    float mu = red[0] * (1.f / DMODEL);
    __syncthreads();
    float d0 = v.x - mu, d1 = v.y - mu, d2 = v.z - mu, d3 = v.w - mu;
    red[t] = d0 * d0 + d1 * d1 + d2 * d2 + d3 * d3;
    __syncthreads();
    for (int off = 128; off > 0; off >>= 1) {
        if (t < off) red[t] += red[t + off];
        __syncthreads();
    }
    float var = red[0] * (1.f / DMODEL);
    float rs = rsqrtf(var + 1e-5f);
    float4 sc = *(const float4*)(s + t * 4);
    float4 be = *(const float4*)(bvec + t * 4);
    float4 out;
    out.x = d0 * rs * sc.x + be.x;
    out.y = d1 * rs * sc.y + be.y;
    out.z = d2 * rs * sc.z + be.z;
    out.w = d3 * rs * sc.w + be.w;
    *(float4*)(Y + (size_t)r * DMODEL + t * 4) = out;
    uint32_t lo0, lo1;
    uint32_t hi0 = pack_split2(out.x, out.y, lo0);
    uint32_t hi1 = pack_split2(out.z, out.w, lo1);
    uint2 hv = {hi0, hi1}, lv = {lo0, lo1};
    *(uint2*)(Yh + (size_t)r * DMODEL + t * 4) = hv;
    *(uint2*)(Yl + (size_t)r * DMODEL + t * 4) = lv;
}

// ---------------- output head ----------------
__global__ void head_kernel(const float* __restrict__ h, const float* __restrict__ ow,
                            const float* __restrict__ ob, float* __restrict__ out) {
    int t = threadIdx.x;
    int b = t >> 4, a = t & 15;
    const float* hrow = h + (size_t)(b * SEQ + (SEQ - 1)) * DMODEL;
    float acc = 0.f;
    for (int m = 0; m < DMODEL; ++m) acc = fmaf(hrow[m], ow[m * 16 + a], acc);
    acc += ob[a];
    float mx = acc;
    for (int off = 8; off > 0; off >>= 1)
        mx = fmaxf(mx, __shfl_xor_sync(0xffffffffu, mx, off));
    float e = expf(acc - mx);
    float sum = e;
    for (int off = 8; off > 0; off >>= 1)
        sum += __shfl_xor_sync(0xffffffffu, sum, off);
    out[b * 16 + a] = acc - mx - logf(sum);
}

// ---------------- launch ----------------
#define M1 1048576u

extern "C" void kernel_launch(void* const* d_in, const int* in_sizes, int n_in,
                              void* d_out, int out_size) {
    const int*   x     = (const int*)d_in[0];
    const int*   mask  = (const int*)d_in[1];
    const float* embed = (const float*)d_in[2];
    const float* Wq    = (const float*)d_in[3];
    const float* Wk    = (const float*)d_in[4];
    const float* Wv    = (const float*)d_in[5];
    const float* Wo_w  = (const float*)d_in[6];
    const float* Wo_b  = (const float*)d_in[7];
    const float* ln1_s = (const float*)d_in[8];
    const float* ln1_b = (const float*)d_in[9];
    const float* ff_w1 = (const float*)d_in[10];
    const float* ff_b1 = (const float*)d_in[11];
    const float* ff_w2 = (const float*)d_in[12];
    const float* ff_b2 = (const float*)d_in[13];
    const float* ln2_s = (const float*)d_in[14];
    const float* ln2_b = (const float*)d_in[15];
    const float* out_w = (const float*)d_in[16];
    const float* out_b = (const float*)d_in[17];
    float* out = (float*)d_out;

    float *h, *tmp, *qkv, *pe;
    unsigned long long* mb;
    bf16 *wtH, *wtL, *hH, *hL, *cxH, *cxL, *ffH, *ffL;
    cudaGetSymbolAddress((void**)&h,   g_h);
    cudaGetSymbolAddress((void**)&tmp, g_tmp);
    cudaGetSymbolAddress((void**)&qkv, g_qkv);
    cudaGetSymbolAddress((void**)&pe,  g_pe);
    cudaGetSymbolAddress((void**)&mb,  g_mb);
    cudaGetSymbolAddress((void**)&wtH, g_wt_hi);
    cudaGetSymbolAddress((void**)&wtL, g_wt_lo);
    cudaGetSymbolAddress((void**)&hH,  g_hh);
    cudaGetSymbolAddress((void**)&hL,  g_hl);
    cudaGetSymbolAddress((void**)&cxH, g_cxh);
    cudaGetSymbolAddress((void**)&cxL, g_cxl);
    cudaGetSymbolAddress((void**)&ffH, g_ffh);
    cudaGetSymbolAddress((void**)&ffL, g_ffl);

    const int flash_smem = (4096 * 3 + 64 * 65 + 3 * 64) * 4;
    cudaFuncSetAttribute(flash_kernel, cudaFuncAttributeMaxDynamicSharedMemorySize, flash_smem);
    cudaFuncSetAttribute(gemm_mma, cudaFuncAttributeMaxDynamicSharedMemorySize, GSMEM);

    pe_kernel<<<(SEQ * DMODEL) / 256, 256>>>(pe);
    maskbits_kernel<<<512, 256>>>(mask, mb);
    embed_kernel<<<BL, 256>>>(x, embed, pe, h, hH, hL);

    // --- weight transpose + split ---
    dim3 tb(32, 8);
    for (int i = 0; i < NLAYERS; ++i) {
        size_t oq = (size_t)i * 3 * M1;
        tsplit_kernel<<<dim3(32, 32), tb>>>(Wq + (size_t)i * NHEADS * DMODEL * DQKV, wtH + oq,        wtL + oq,        DMODEL, DMODEL, 1);
        tsplit_kernel<<<dim3(32, 32), tb>>>(Wk + (size_t)i * NHEADS * DMODEL * DQKV, wtH + oq + M1,   wtL + oq + M1,   DMODEL, DMODEL, 1);
        tsplit_kernel<<<dim3(32, 32), tb>>>(Wv + (size_t)i * NHEADS * DMODEL * DQKV, wtH + oq + 2*M1, wtL + oq + 2*M1, DMODEL, DMODEL, 1);
        size_t oo = 18 * (size_t)M1 + (size_t)i * M1;
        tsplit_kernel<<<dim3(32, 32), tb>>>(Wo_w + (size_t)i * DMODEL * DMODEL, wtH + oo, wtL + oo, DMODEL, DMODEL, 0);
        size_t o1 = 24 * (size_t)M1 + (size_t)i * 4 * M1;
        tsplit_kernel<<<dim3(128, 32), tb>>>(ff_w1 + (size_t)i * DMODEL * DFF, wtH + o1, wtL + o1, DMODEL, DFF, 0);
        size_t o2 = 48 * (size_t)M1 + (size_t)i * 4 * M1;
        tsplit_kernel<<<dim3(32, 128), tb>>>(ff_w2 + (size_t)i * DFF * DMODEL, wtH + o2, wtL + o2, DFF, DMODEL, 0);
    }

    dim3 gQKV(D3 / BNT, BL / BMT);   // (24, 64)
    dim3 gD(DMODEL / BNT, BL / BMT); // (8, 64)
    dim3 gF(DFF / BNT, BL / BMT);    // (32, 64)

    for (int i = 0; i < NLAYERS; ++i) {
        size_t oq = (size_t)i * 3 * M1;
        size_t oo = 18 * (size_t)M1 + (size_t)i * M1;
        size_t o1 = 24 * (size_t)M1 + (size_t)i * 4 * M1;
        size_t o2 = 48 * (size_t)M1 + (size_t)i * 4 * M1;

        // fused QKV: [BL, 3072]
        gemm_mma<<<gQKV, 256, GSMEM>>>(hH, hL, wtH + oq, wtL + oq, qkv, nullptr, nullptr,
                                       D3, DMODEL, nullptr, nullptr, 0);

        flash_kernel<<<dim3(SEQ / 64, NHEADS, BATCH), 256, flash_smem>>>(qkv, mb, cxH, cxL);

        // Wo + residual -> tmp, then LN1 -> h + split
        gemm_mma<<<gD, 256, GSMEM>>>(cxH, cxL, wtH + oo, wtL + oo, tmp, nullptr, nullptr,
                                     DMODEL, DMODEL, Wo_b + (size_t)i * DMODEL, h, 0);
        layernorm_kernel<<<BL, 256>>>(tmp, ln1_s + (size_t)i * DMODEL, ln1_b + (size_t)i * DMODEL, h, hH, hL);

        // FF1 (relu) -> split only
        gemm_mma<<<gF, 256, GSMEM>>>(hH, hL, wtH + o1, wtL + o1, nullptr, ffH, ffL,
                                     DFF, DMODEL, ff_b1 + (size_t)i * DFF, nullptr, 1);
        // FF2 + residual -> tmp, then LN2 -> h + split
        gemm_mma<<<gD, 256, GSMEM>>>(ffH, ffL, wtH + o2, wtL + o2, tmp, nullptr, nullptr,
                                     DMODEL, DFF, ff_b2 + (size_t)i * DMODEL, h, 0);
        layernorm_kernel<<<BL, 256>>>(tmp, ln2_s + (size_t)i * DMODEL, ln2_b + (size_t)i * DMODEL, h, hH, hL);
    }

    head_kernel<<<1, 128>>>(h, out_w, out_b, out);
}

// round 7
// speedup vs baseline: 1.0845x; 1.0015x over previous
#include <cuda_runtime.h>
#include <cuda_bf16.h>
#include <math.h>
#include <stdint.h>

// ---------------- dims ----------------
#define BATCH 8
#define SEQ   1024
#define DMODEL 1024
#define NHEADS 16
#define DQKV  64
#define DFF   4096
#define NLAYERS 6
#define BL    (BATCH*SEQ)          // 8192
#define D3    (3*DMODEL)           // 3072

typedef __nv_bfloat16 bf16;

// ---------------- scratch ----------------
__device__ float g_h  [BL*DMODEL];
__device__ float g_tmp[BL*DMODEL];
__device__ float g_qkv[BL*D3];
__device__ float g_pe [SEQ*DMODEL];
__device__ unsigned long long g_mb[BL*(SEQ/64)];

// split activations
__device__ bf16 g_hh [BL*DMODEL];
__device__ bf16 g_hl [BL*DMODEL];
__device__ bf16 g_cxh[BL*DMODEL];
__device__ bf16 g_cxl[BL*DMODEL];
__device__ bf16 g_ffh[BL*DFF];
__device__ bf16 g_ffl[BL*DFF];

// transposed + split weights (bf16 hi/lo), layout [N][K] K-major
#define WT_TOTAL (72u*1048576u)
__device__ bf16 g_wt_hi[WT_TOTAL];
__device__ bf16 g_wt_lo[WT_TOTAL];

// ================= PTX helpers =================
__device__ __forceinline__ uint32_t smem_u32(const void* p) {
    uint32_t a;
    asm("{ .reg .u64 t; cvta.to.shared.u64 t, %1; cvt.u32.u64 %0, t; }" : "=r"(a) : "l"(p));
    return a;
}
__device__ __forceinline__ void cp16(uint32_t s, const void* g) {
    asm volatile("cp.async.cg.shared.global [%0], [%1], 16;" :: "r"(s), "l"(g));
}
__device__ __forceinline__ void cp_commit() { asm volatile("cp.async.commit_group;"); }
template <int N> __device__ __forceinline__ void cp_wait() {
    asm volatile("cp.async.wait_group %0;" :: "n"(N));
}
__device__ __forceinline__ void ldm4(uint32_t& r0, uint32_t& r1, uint32_t& r2, uint32_t& r3, uint32_t a) {
    asm volatile("ldmatrix.sync.aligned.m8n8.x4.shared.b16 {%0,%1,%2,%3}, [%4];"
        : "=r"(r0), "=r"(r1), "=r"(r2), "=r"(r3) : "r"(a));
}
__device__ __forceinline__ void mma16816(float* c, uint32_t a0, uint32_t a1, uint32_t a2, uint32_t a3,
                                         uint32_t b0, uint32_t b1) {
    asm volatile("mma.sync.aligned.m16n8k16.row.col.f32.bf16.bf16.f32 "
        "{%0,%1,%2,%3}, {%4,%5,%6,%7}, {%8,%9}, {%0,%1,%2,%3};"
        : "+f"(c[0]), "+f"(c[1]), "+f"(c[2]), "+f"(c[3])
        : "r"(a0), "r"(a1), "r"(a2), "r"(a3), "r"(b0), "r"(b1));
}
__device__ __forceinline__ uint32_t pack_split2(float v0, float v1, uint32_t& lo_out) {
    bf16 h0 = __float2bfloat16(v0);
    bf16 h1 = __float2bfloat16(v1);
    bf16 l0 = __float2bfloat16(v0 - __bfloat162float(h0));
    bf16 l1 = __float2bfloat16(v1 - __bfloat162float(h1));
    uint32_t hi = ((uint32_t)*(uint16_t*)&h1 << 16) | *(uint16_t*)&h0;
    lo_out = ((uint32_t)*(uint16_t*)&l1 << 16) | *(uint16_t*)&l0;
    return hi;
}

// ---------------- positional encoding ----------------
__global__ void pe_kernel(float* pe) {
    int idx = blockIdx.x * blockDim.x + threadIdx.x;
    int l = idx >> 10;
    int c = idx & 1023;
    double p = (double)(c & ~1) / (double)DMODEL;
    double divisor = pow(10000.0, p);
    double ang = (double)(l + 1) / divisor;
    pe[idx] = (float)((c & 1) ? cos(ang) : sin(ang));
}

// ---------------- mask -> bit words ----------------
__global__ void maskbits_kernel(const int* __restrict__ mask, unsigned long long* __restrict__ mb) {
    int warp = (blockIdx.x * blockDim.x + threadIdx.x) >> 5;
    int lane = threadIdx.x & 31;
    const int nwarps = gridDim.x * blockDim.x / 32;
    for (int w = warp; w < BL * (SEQ/64); w += nwarps) {
        int row = w >> 4;
        int kt  = w & 15;
        size_t base = (size_t)row * SEQ + kt * 64;
        int m0 = mask[base + lane];
        int m1 = mask[base + 32 + lane];
        unsigned lo = __ballot_sync(0xffffffffu, m0 != 0);
        unsigned hi = __ballot_sync(0xffffffffu, m1 != 0);
        if (lane == 0) mb[w] = (unsigned long long)lo | ((unsigned long long)hi << 32);
    }
}

// ---------------- embedding + PE (+ split) ----------------
__global__ void embed_kernel(const int* __restrict__ x, const float* __restrict__ embed,
                             const float* __restrict__ pe, float* __restrict__ h,
                             bf16* __restrict__ Hh, bf16* __restrict__ Hl) {
    int r = blockIdx.x;
    int t = threadIdx.x;
    int l = r & 1023;
    int tok = x[r];
    float4 e  = *(const float4*)(embed + (size_t)tok * DMODEL + t * 4);
    float4 pp = *(const float4*)(pe + (size_t)l * DMODEL + t * 4);
    float4 o;
    o.x = e.x * 32.0f + pp.x;
    o.y = e.y * 32.0f + pp.y;
    o.z = e.z * 32.0f + pp.z;
    o.w = e.w * 32.0f + pp.w;
    *(float4*)(h + (size_t)r * DMODEL + t * 4) = o;
    uint32_t hi0, hi1, lo0, lo1;
    hi0 = pack_split2(o.x, o.y, lo0);
    hi1 = pack_split2(o.z, o.w, lo1);
    uint2 hv = {hi0, hi1}, lv = {lo0, lo1};
    *(uint2*)(Hh + (size_t)r * DMODEL + t * 4) = hv;
    *(uint2*)(Hl + (size_t)r * DMODEL + t * 4) = lv;
}

// ---------------- weight transpose + bf16 split ----------------
// mode 0: src [K][N] -> dst [N][K].  mode 1: src [H][K][64]
__device__ __forceinline__ void tsplit_body(const float* W, bf16* Oh, bf16* Ol,
                                            int K, int N, int mode) {
    __shared__ float tile[32][33];
    int n0 = blockIdx.x * 32, k0 = blockIdx.y * 32;
    int tx = threadIdx.x, ty = threadIdx.y;    // 32 x 8
#pragma unroll
    for (int i = 0; i < 32; i += 8) {
        int k = k0 + ty + i, n = n0 + tx;
        float v;
        if (mode == 0) v = W[(size_t)k * N + n];
        else v = W[(size_t)(n >> 6) * (K * 64) + (size_t)k * 64 + (n & 63)];
        tile[ty + i][tx] = v;
    }
    __syncthreads();
#pragma unroll
    for (int i = 0; i < 32; i += 8) {
        int n = n0 + ty + i, k = k0 + tx;
        float v = tile[tx][ty + i];
        bf16 hi = __float2bfloat16(v);
        bf16 lo = __float2bfloat16(v - __bfloat162float(hi));
        Oh[(size_t)n * K + k] = hi;
        Ol[(size_t)n * K + k] = lo;
    }
}

__global__ void tsplit_kernel(const float* __restrict__ W, bf16* __restrict__ Oh, bf16* __restrict__ Ol,
                              int K, int N, int mode) {
    tsplit_body(W, Oh, Ol, K, N, mode);
}

// fused q/k/v tsplit: gridDim.z = 3 selects matrix; outputs contiguous 1M apart
#define M1 1048576u
__global__ void tsplit_qkv_kernel(const float* __restrict__ Wq, const float* __restrict__ Wk,
                                  const float* __restrict__ Wv, bf16* __restrict__ Oh,
                                  bf16* __restrict__ Ol) {
    int z = blockIdx.z;
    const float* W = (z == 0) ? Wq : (z == 1) ? Wk : Wv;
    tsplit_body(W, Oh + (size_t)z * M1, Ol + (size_t)z * M1, DMODEL, DMODEL, 1);
}

// ---------------- HMMA GEMM, 2-stage cp.async, 2 CTAs/SM ----------------
#define BMT 128
#define BNT 128
#define BKC 32
#define TSTRIDE 40                         // bf16 per smem row (pad 8)
#define TILEB (BMT * TSTRIDE * 2)          // 10240 B
#define STAGEB (4 * TILEB)                 // 40960 B
#define GSMEM (2 * STAGEB)                 // 81920 B

__global__ void __launch_bounds__(256, 2)
gemm_mma(const bf16* __restrict__ Ah, const bf16* __restrict__ Al,
         const bf16* __restrict__ Bh, const bf16* __restrict__ Bl,
         float* __restrict__ C, bf16* __restrict__ Oh, bf16* __restrict__ Ol,
         int N, int K,
         const float* __restrict__ bias, const float* __restrict__ res, int relu) {
    extern __shared__ char smem[];
    const uint32_t sbase = smem_u32(smem);
    const int t = threadIdx.x;
    const int wid = t >> 5, lane = t & 31;
    const int wm = wid >> 2, wn = wid & 3;       // 2 x 4 warps
    const int row0 = blockIdx.y * BMT, col0 = blockIdx.x * BNT;

    const bf16* srcs[4];
    srcs[0] = Ah + (size_t)row0 * K;
    srcs[1] = Al + (size_t)row0 * K;
    srcs[2] = Bh + (size_t)col0 * K;
    srcs[3] = Bl + (size_t)col0 * K;

    const int nst = K / BKC;
    const int lrow0 = t >> 2, lchunk = t & 3;

    auto load_stage = [&](int kc, int buf) {
        uint32_t sb = sbase + buf * STAGEB;
#pragma unroll
        for (int m = 0; m < 4; ++m) {
            const bf16* g = srcs[m] + (size_t)kc * BKC;
            uint32_t tb = sb + m * TILEB;
#pragma unroll
            for (int hlf = 0; hlf < 2; ++hlf) {
                int row = lrow0 + hlf * 64;
                cp16(tb + (row * TSTRIDE + lchunk * 8) * 2,
                     g + (size_t)row * K + lchunk * 8);
            }
        }
        cp_commit();
    };

    float acc[4][4][4];
#pragma unroll
    for (int i = 0; i < 4; ++i)
#pragma unroll
        for (int j = 0; j < 4; ++j)
#pragma unroll
            for (int r = 0; r < 4; ++r) acc[i][j][r] = 0.f;

    const int lrow = lane & 15;
    const int lcol = (lane >> 4) << 3;

    load_stage(0, 0);

    for (int kc = 0; kc < nst; ++kc) {
        int buf = kc & 1;
        if (kc + 1 < nst) {
            load_stage(kc + 1, buf ^ 1);
            cp_wait<1>();
        } else {
            cp_wait<0>();
        }
        __syncthreads();

        uint32_t sb = sbase + buf * STAGEB;
        uint32_t sAh = sb;
        uint32_t sAl = sb + TILEB;
        uint32_t sBh = sb + 2 * TILEB;
        uint32_t sBl = sb + 3 * TILEB;

#pragma unroll
        for (int ks = 0; ks < 2; ++ks) {
            int kof = ks * 16 + lcol;
            uint32_t ah[4][4], al[4][4];
#pragma unroll
            for (int mi = 0; mi < 4; ++mi) {
                int row = wm * 64 + mi * 16 + lrow;
                uint32_t off = (row * TSTRIDE + kof) * 2;
                ldm4(ah[mi][0], ah[mi][1], ah[mi][2], ah[mi][3], sAh + off);
                ldm4(al[mi][0], al[mi][1], al[mi][2], al[mi][3], sAl + off);
            }
            uint32_t bh[2][4], bl[2][4];
#pragma unroll
            for (int nh = 0; nh < 2; ++nh) {
                int row = wn * 32 + nh * 16 + lrow;
                uint32_t off = (row * TSTRIDE + kof) * 2;
                ldm4(bh[nh][0], bh[nh][1], bh[nh][2], bh[nh][3], sBh + off);
                ldm4(bl[nh][0], bl[nh][1], bl[nh][2], bl[nh][3], sBl + off);
            }
#pragma unroll
            for (int mi = 0; mi < 4; ++mi) {
#pragma unroll
                for (int ni = 0; ni < 4; ++ni) {
                    int nh = ni >> 1, np = ni & 1;
                    uint32_t b0h = bh[nh][np], b1h = bh[nh][np + 2];
                    uint32_t b0l = bl[nh][np], b1l = bl[nh][np + 2];
                    mma16816(acc[mi][ni], ah[mi][0], ah[mi][1], ah[mi][2], ah[mi][3], b0h, b1h);
                    mma16816(acc[mi][ni], ah[mi][0], ah[mi][1], ah[mi][2], ah[mi][3], b0l, b1l);
                    mma16816(acc[mi][ni], al[mi][0], al[mi][1], al[mi][2], al[mi][3], b0h, b1h);
                }
            }
        }
        __syncthreads();
    }

    // epilogue
    const int erow = lane >> 2, ecol = (lane & 3) * 2;
#pragma unroll
    for (int mi = 0; mi < 4; ++mi) {
#pragma unroll
        for (int p = 0; p < 2; ++p) {
            int r = row0 + wm * 64 + mi * 16 + p * 8 + erow;
            const float* rrow = res ? res + (size_t)r * N : (const float*)0;
#pragma unroll
            for (int ni = 0; ni < 4; ++ni) {
                int c = col0 + wn * 32 + ni * 8 + ecol;
                float v0 = acc[mi][ni][p * 2 + 0];
                float v1 = acc[mi][ni][p * 2 + 1];
                if (bias) { v0 += bias[c]; v1 += bias[c + 1]; }
                if (rrow) {
                    float2 rv = *(const float2*)(rrow + c);
                    v0 += rv.x; v1 += rv.y;
                }
                if (relu) { v0 = fmaxf(v0, 0.f); v1 = fmaxf(v1, 0.f); }
                if (C) {
                    float2 o = {v0, v1};
                    *(float2*)(C + (size_t)r * N + c) = o;
                }
                if (Oh) {
                    uint32_t lo, hi = pack_split2(v0, v1, lo);
                    *(uint32_t*)(Oh + (size_t)r * N + c) = hi;
                    *(uint32_t*)(Ol + (size_t)r * N + c) = lo;
                }
            }
        }
    }
}

// ---------------- flash attention (fp32, split ctx output) ----------------
#define QSW(d, r) (((d) << 6) + (((((r) >> 2) ^ ((d) & 15))) << 2) + ((r) & 3))

__global__ void __launch_bounds__(256)
flash_kernel(const float* __restrict__ qkv, const unsigned long long* __restrict__ mb,
             bf16* __restrict__ cxh, bf16* __restrict__ cxl) {
    extern __shared__ float sm[];
    float* Qs = sm;
    float* Ks = Qs + 4096;
    float* Vs = Ks + 4096;
    float* Ss = Vs + 4096;
    float* rowM = Ss + 64 * 65;
    float* rowL = rowM + 64;
    float* rowA = rowL + 64;

    int b = blockIdx.z, hh = blockIdx.y, qt = blockIdx.x;
    int t = threadIdx.x, tx = t & 15, ty = t >> 4;
    int rowbase = b * SEQ + qt * 64;
    const float* qbase = qkv + (size_t)rowbase * D3 + hh * 64;

#pragma unroll
    for (int it = 0; it < 4; ++it) {
        int f = t + it * 256;
        int r = f >> 4;
        int d4 = (f & 15) << 2;
        float4 val = *(const float4*)(qbase + (size_t)r * D3 + d4);
        Qs[QSW(d4 + 0, r)] = val.x;
        Qs[QSW(d4 + 1, r)] = val.y;
        Qs[QSW(d4 + 2, r)] = val.z;
        Qs[QSW(d4 + 3, r)] = val.w;
    }
    if (t < 64) { rowM[t] = -INFINITY; rowL[t] = 0.f; }

    float o[4][4];
#pragma unroll
    for (int i = 0; i < 4; ++i)
#pragma unroll
        for (int j = 0; j < 4; ++j) o[i][j] = 0.f;

    const unsigned long long* mrow = mb + (size_t)rowbase * (SEQ / 64);

    for (int kt = 0; kt < SEQ / 64; ++kt) {
        __syncthreads();
        const float* kbase = qkv + (size_t)(b * SEQ + kt * 64) * D3 + DMODEL + hh * 64;
        const float* vbase = qkv + (size_t)(b * SEQ + kt * 64) * D3 + 2 * DMODEL + hh * 64;
#pragma unroll
        for (int it = 0; it < 4; ++it) {
            int f = t + it * 256;
            int r = f >> 4;
            int d4 = (f & 15) << 2;
            float4 kv4 = *(const float4*)(kbase + (size_t)r * D3 + d4);
            Ks[QSW(d4 + 0, r)] = kv4.x;
            Ks[QSW(d4 + 1, r)] = kv4.y;
            Ks[QSW(d4 + 2, r)] = kv4.z;
            Ks[QSW(d4 + 3, r)] = kv4.w;
            float4 vv = *(const float4*)(vbase + (size_t)r * D3 + d4);
            *(float4*)(Vs + r * 64 + d4) = vv;
        }
        __syncthreads();

        float s[4][4];
#pragma unroll
        for (int i = 0; i < 4; ++i)
#pragma unroll
            for (int j = 0; j < 4; ++j) s[i][j] = 0.f;
#pragma unroll 8
        for (int d = 0; d < 64; ++d) {
            float4 a4 = *(const float4*)(Qs + (d << 6) + ((ty ^ (d & 15)) << 2));
            float4 b4 = *(const float4*)(Ks + (d << 6) + ((tx ^ (d & 15)) << 2));
            float a[4] = {a4.x, a4.y, a4.z, a4.w};
            float bb[4] = {b4.x, b4.y, b4.z, b4.w};
#pragma unroll
            for (int i = 0; i < 4; ++i)
#pragma unroll
                for (int j = 0; j < 4; ++j) s[i][j] = fmaf(a[i], bb[j], s[i][j]);
        }
#pragma unroll
        for (int i = 0; i < 4; ++i) {
            int ri = ty * 4 + i;
            unsigned long long wbits = mrow[ri * (SEQ / 64) + kt];
#pragma unroll
            for (int j = 0; j < 4; ++j) {
                int cj = tx * 4 + j;
                float vv = s[i][j] * 0.125f;
                if (!((wbits >> cj) & 1ULL)) vv = -1e9f;
                Ss[ri * 65 + cj] = vv;
            }
        }
        __syncthreads();

        // online softmax: 4 threads per row
        {
            int r = t >> 2, sub = t & 3;
            float* srow = Ss + r * 65 + sub * 16;
            float mold = rowM[r];
            float mx = mold;
#pragma unroll
            for (int j = 0; j < 16; ++j) mx = fmaxf(mx, srow[j]);
            mx = fmaxf(mx, __shfl_xor_sync(0xffffffffu, mx, 1));
            mx = fmaxf(mx, __shfl_xor_sync(0xffffffffu, mx, 2));
            float sum = 0.f;
#pragma unroll
            for (int j = 0; j < 16; ++j) {
                float p = expf(srow[j] - mx);
                srow[j] = p;
                sum += p;
            }
            sum += __shfl_xor_sync(0xffffffffu, sum, 1);
            sum += __shfl_xor_sync(0xffffffffu, sum, 2);
            if (sub == 0) {
                float alpha = expf(mold - mx);
                rowL[r] = rowL[r] * alpha + sum;
                rowM[r] = mx;
                rowA[r] = alpha;
            }
        }
        __syncthreads();

        float al[4];
#pragma unroll
        for (int i = 0; i < 4; ++i) al[i] = rowA[ty * 4 + i];
#pragma unroll
        for (int i = 0; i < 4; ++i)
#pragma unroll
            for (int j = 0; j < 4; ++j) o[i][j] *= al[i];
#pragma unroll 8
        for (int j = 0; j < 64; ++j) {
            float p0 = Ss[(ty * 4 + 0) * 65 + j];
            float p1 = Ss[(ty * 4 + 1) * 65 + j];
            float p2 = Ss[(ty * 4 + 2) * 65 + j];
            float p3 = Ss[(ty * 4 + 3) * 65 + j];
            float4 vv = *(const float4*)(Vs + j * 64 + tx * 4);
            o[0][0] = fmaf(p0, vv.x, o[0][0]); o[0][1] = fmaf(p0, vv.y, o[0][1]);
            o[0][2] = fmaf(p0, vv.z, o[0][2]); o[0][3] = fmaf(p0, vv.w, o[0][3]);
            o[1][0] = fmaf(p1, vv.x, o[1][0]); o[1][1] = fmaf(p1, vv.y, o[1][1]);
            o[1][2] = fmaf(p1, vv.z, o[1][2]); o[1][3] = fmaf(p1, vv.w, o[1][3]);
            o[2][0] = fmaf(p2, vv.x, o[2][0]); o[2][1] = fmaf(p2, vv.y, o[2][1]);
            o[2][2] = fmaf(p2, vv.z, o[2][2]); o[2][3] = fmaf(p2, vv.w, o[2][3]);
            o[3][0] = fmaf(p3, vv.x, o[3][0]); o[3][1] = fmaf(p3, vv.y, o[3][1]);
            o[3][2] = fmaf(p3, vv.z, o[3][2]); o[3][3] = fmaf(p3, vv.w, o[3][3]);
        }
    }
    __syncthreads();
#pragma unroll
    for (int i = 0; i < 4; ++i) {
        float inv = 1.f / rowL[ty * 4 + i];
        int grow = rowbase + ty * 4 + i;
        float v0 = o[i][0] * inv, v1 = o[i][1] * inv, v2 = o[i][2] * inv, v3 = o[i][3] * inv;
        uint32_t lo0, lo1;
        uint32_t hi0 = pack_split2(v0, v1, lo0);
        uint32_t hi1 = pack_split2(v2, v3, lo1);
        uint2 hv = {hi0, hi1}, lv = {lo0, lo1};
        size_t off = (size_t)grow * DMODEL + hh * 64 + tx * 4;
        *(uint2*)(cxh + off) = hv;
        *(uint2*)(cxl + off) = lv;
    }
}

// ---------------- layernorm (+ split out) ----------------
__global__ void layernorm_kernel(const float* __restrict__ X, const float* __restrict__ s,
                                 const float* __restrict__ bvec, float* __restrict__ Y,
                                 bf16* __restrict__ Yh, bf16* __restrict__ Yl) {
    __shared__ float red[256];
    int r = blockIdx.x;
    int t = threadIdx.x;
    float4 v = *(const float4*)(X + (size_t)r * DMODEL + t * 4);
    float ssum = v.x + v.y + v.z + v.w;
    red[t] = ssum;
    __syncthreads();
    for (int off = 128; off > 0; off >>= 1) {
        if (t < off) red[t] += red[t + off];
        __syncthreads();
    }
    float mu = red[0] * (1.f / DMODEL);
    __syncthreads();
    float d0 = v.x - mu, d1 = v.y - mu, d2 = v.z - mu, d3 = v.w - mu;
    red[t] = d0 * d0 + d1 * d1 + d2 * d2 + d3 * d3;
    __syncthreads();
    for (int off = 128; off > 0; off >>= 1) {
        if (t < off) red[t] += red[t + off];
        __syncthreads();
    }
    float var = red[0] * (1.f / DMODEL);
    float rs = rsqrtf(var + 1e-5f);
    float4 sc = *(const float4*)(s + t * 4);
    float4 be = *(const float4*)(bvec + t * 4);
    float4 out;
    out.x = d0 * rs * sc.x + be.x;
    out.y = d1 * rs * sc.y + be.y;
    out.z = d2 * rs * sc.z + be.z;
    out.w = d3 * rs * sc.w + be.w;
    *(float4*)(Y + (size_t)r * DMODEL + t * 4) = out;
    uint32_t lo0, lo1;
    uint32_t hi0 = pack_split2(out.x, out.y, lo0);
    uint32_t hi1 = pack_split2(out.z, out.w, lo1);
    uint2 hv = {hi0, hi1}, lv = {lo0, lo1};
    *(uint2*)(Yh + (size_t)r * DMODEL + t * 4) = hv;
    *(uint2*)(Yl + (size_t)r * DMODEL + t * 4) = lv;
}

// ---------------- output head ----------------
__global__ void head_kernel(const float* __restrict__ h, const float* __restrict__ ow,
                            const float* __restrict__ ob, float* __restrict__ out) {
    int t = threadIdx.x;
    int b = t >> 4, a = t & 15;
    const float* hrow = h + (size_t)(b * SEQ + (SEQ - 1)) * DMODEL;
    float acc = 0.f;
    for (int m = 0; m < DMODEL; ++m) acc = fmaf(hrow[m], ow[m * 16 + a], acc);
    acc += ob[a];
    float mx = acc;
    for (int off = 8; off > 0; off >>= 1)
        mx = fmaxf(mx, __shfl_xor_sync(0xffffffffu, mx, off));
    float e = expf(acc - mx);
    float sum = e;
    for (int off = 8; off > 0; off >>= 1)
        sum += __shfl_xor_sync(0xffffffffu, sum, off);
    out[b * 16 + a] = acc - mx - logf(sum);
}

// ---------------- launch ----------------
extern "C" void kernel_launch(void* const* d_in, const int* in_sizes, int n_in,
                              void* d_out, int out_size) {
    const int*   x     = (const int*)d_in[0];
    const int*   mask  = (const int*)d_in[1];
    const float* embed = (const float*)d_in[2];
    const float* Wq    = (const float*)d_in[3];
    const float* Wk    = (const float*)d_in[4];
    const float* Wv    = (const float*)d_in[5];
    const float* Wo_w  = (const float*)d_in[6];
    const float* Wo_b  = (const float*)d_in[7];
    const float* ln1_s = (const float*)d_in[8];
    const float* ln1_b = (const float*)d_in[9];
    const float* ff_w1 = (const float*)d_in[10];
    const float* ff_b1 = (const float*)d_in[11];
    const float* ff_w2 = (const float*)d_in[12];
    const float* ff_b2 = (const float*)d_in[13];
    const float* ln2_s = (const float*)d_in[14];
    const float* ln2_b = (const float*)d_in[15];
    const float* out_w = (const float*)d_in[16];
    const float* out_b = (const float*)d_in[17];
    float* out = (float*)d_out;

    float *h, *tmp, *qkv, *pe;
    unsigned long long* mb;
    bf16 *wtH, *wtL, *hH, *hL, *cxH, *cxL, *ffH, *ffL;
    cudaGetSymbolAddress((void**)&h,   g_h);
    cudaGetSymbolAddress((void**)&tmp, g_tmp);
    cudaGetSymbolAddress((void**)&qkv, g_qkv);
    cudaGetSymbolAddress((void**)&pe,  g_pe);
    cudaGetSymbolAddress((void**)&mb,  g_mb);
    cudaGetSymbolAddress((void**)&wtH, g_wt_hi);
    cudaGetSymbolAddress((void**)&wtL, g_wt_lo);
    cudaGetSymbolAddress((void**)&hH,  g_hh);
    cudaGetSymbolAddress((void**)&hL,  g_hl);
    cudaGetSymbolAddress((void**)&cxH, g_cxh);
    cudaGetSymbolAddress((void**)&cxL, g_cxl);
    cudaGetSymbolAddress((void**)&ffH, g_ffh);
    cudaGetSymbolAddress((void**)&ffL, g_ffl);

    const int flash_smem = (4096 * 3 + 64 * 65 + 3 * 64) * 4;
    cudaFuncSetAttribute(flash_kernel, cudaFuncAttributeMaxDynamicSharedMemorySize, flash_smem);
    cudaFuncSetAttribute(gemm_mma, cudaFuncAttributeMaxDynamicSharedMemorySize, GSMEM);

    dim3 tb(32, 8);
    dim3 gQKV(D3 / BNT, BL / BMT);   // (24, 64)
    dim3 gD(DMODEL / BNT, BL / BMT); // (8, 64)
    dim3 gF(DFF / BNT, BL / BMT);    // (32, 64)

    // Launch order chosen so launch index 5 (ncu -s 5 -c 1) is the first gemm_mma.
    pe_kernel<<<(SEQ * DMODEL) / 256, 256>>>(pe);                       // 0
    maskbits_kernel<<<512, 256>>>(mask, mb);                            // 1
    embed_kernel<<<BL, 256>>>(x, embed, pe, h, hH, hL);                 // 2

    for (int i = 0; i < NLAYERS; ++i) {
        size_t oq = (size_t)i * 3 * M1;
        size_t oo = 18 * (size_t)M1 + (size_t)i * M1;
        size_t o1 = 24 * (size_t)M1 + (size_t)i * 4 * M1;
        size_t o2 = 48 * (size_t)M1 + (size_t)i * 4 * M1;

        // per-layer weight prep (layer 0: launches 3,4 -> gemm at 5)
        tsplit_qkv_kernel<<<dim3(32, 32, 3), tb>>>(
            Wq + (size_t)i * NHEADS * DMODEL * DQKV,
            Wk + (size_t)i * NHEADS * DMODEL * DQKV,
            Wv + (size_t)i * NHEADS * DMODEL * DQKV,
            wtH + oq, wtL + oq);                                        // 3
        tsplit_kernel<<<dim3(32, 32), tb>>>(Wo_w + (size_t)i * DMODEL * DMODEL,
                                            wtH + oo, wtL + oo, DMODEL, DMODEL, 0);  // 4

        // fused QKV: [BL, 3072]                                        // 5 (profiled)
        gemm_mma<<<gQKV, 256, GSMEM>>>(hH, hL, wtH + oq, wtL + oq, qkv, nullptr, nullptr,
                                       D3, DMODEL, nullptr, nullptr, 0);

        tsplit_kernel<<<dim3(128, 32), tb>>>(ff_w1 + (size_t)i * DMODEL * DFF,
                                             wtH + o1, wtL + o1, DMODEL, DFF, 0);
        tsplit_kernel<<<dim3(32, 128), tb>>>(ff_w2 + (size_t)i * DFF * DMODEL,
                                             wtH + o2, wtL + o2, DFF, DMODEL, 0);

        flash_kernel<<<dim3(SEQ / 64, NHEADS, BATCH), 256, flash_smem>>>(qkv, mb, cxH, cxL);

        gemm_mma<<<gD, 256, GSMEM>>>(cxH, cxL, wtH + oo, wtL + oo, tmp, nullptr, nullptr,
                                     DMODEL, DMODEL, Wo_b + (size_t)i * DMODEL, h, 0);
        layernorm_kernel<<<BL, 256>>>(tmp, ln1_s + (size_t)i * DMODEL, ln1_b + (size_t)i * DMODEL, h, hH, hL);

        gemm_mma<<<gF, 256, GSMEM>>>(hH, hL, wtH + o1, wtL + o1, nullptr, ffH, ffL,
                                     DFF, DMODEL, ff_b1 + (size_t)i * DFF, nullptr, 1);
        gemm_mma<<<gD, 256, GSMEM>>>(ffH, ffL, wtH + o2, wtL + o2, tmp, nullptr, nullptr,
                                     DMODEL, DFF, ff_b2 + (size_t)i * DMODEL, h, 0);
        layernorm_kernel<<<BL, 256>>>(tmp, ln2_s + (size_t)i * DMODEL, ln2_b + (size_t)i * DMODEL, h, hH, hL);
    }

    head_kernel<<<1, 128>>>(h, out_w, out_b, out);
}